// round 1
// baseline (speedup 1.0000x reference)
#include <cuda_runtime.h>
#include <cstdint>
#include <math.h>

// Problem constants
#define BB    2
#define NN    2048
#define KK    32
#define HH    128
#define NODES 4096          // B*N
#define EDGES 131072        // B*N*K
#define PAD   130           // smem row stride (floats) for 128-wide tiles

// ---------------- scratch (static device globals; no runtime alloc) ----------
__device__ float g_he [EDGES * HH];   // 64 MiB: normalized edge embeddings
__device__ float g_h  [NODES * HH];   // current node state
__device__ float g_P1 [NODES * HH];   // h@W1 + b1
__device__ float g_P23[NODES * HH];   // h@W2 + hS@W3

// ---------------- packed f32x2 helpers --------------------------------------
__device__ __forceinline__ void ffma2(unsigned long long &c,
                                      unsigned long long a,
                                      unsigned long long b) {
    asm("fma.rn.f32x2 %0, %1, %2, %0;" : "+l"(c) : "l"(a), "l"(b));
}
__device__ __forceinline__ unsigned long long pack2(float a) {
    unsigned long long r;
    asm("mov.b64 %0, {%1, %1};" : "=l"(r) : "f"(a));
    return r;
}
__device__ __forceinline__ float2 u2f(unsigned long long u) {
    float2 f;
    asm("mov.b64 {%0, %1}, %2;" : "=f"(f.x), "=f"(f.y) : "l"(u));
    return f;
}

// 128x128 (K=128) block GEMM: out[r][j] += sum_kk sA[r*PAD+kk] * sW[kk*128+j]
// thread mapping: 256 threads, j0=(tid&15)*8 cols, r0=(tid>>4)*8 rows
__device__ __forceinline__ void gemm_tile(const float* __restrict__ sA,
                                          const float* __restrict__ sW,
                                          int r0, int j0,
                                          unsigned long long acc[8][4]) {
#pragma unroll 4
    for (int kk = 0; kk < 128; ++kk) {
        ulonglong2 w01 = *reinterpret_cast<const ulonglong2*>(sW + kk * 128 + j0);
        ulonglong2 w23 = *reinterpret_cast<const ulonglong2*>(sW + kk * 128 + j0 + 4);
#pragma unroll
        for (int i = 0; i < 8; ++i) {
            unsigned long long a2 = pack2(sA[(r0 + i) * PAD + kk]);
            ffma2(acc[i][0], a2, w01.x);
            ffma2(acc[i][1], a2, w01.y);
            ffma2(acc[i][2], a2, w23.x);
            ffma2(acc[i][3], a2, w23.y);
        }
    }
}

__device__ __forceinline__ void zero_acc(unsigned long long acc[8][4]) {
#pragma unroll
    for (int i = 0; i < 8; ++i)
#pragma unroll
        for (int c = 0; c < 4; ++c) acc[i][c] = 0ull;
}

// load 128x128 f32 tile (contiguous) into padded smem
__device__ __forceinline__ void load_tile_pad(float* dst, const float* __restrict__ src, int tid) {
    for (int i = tid * 2; i < 128 * 128; i += 512) {
        float2 v = *reinterpret_cast<const float2*>(src + i);
        int r = i >> 7, c = i & 127;
        *reinterpret_cast<float2*>(dst + r * PAD + c) = v;
    }
}
// load 128x128 f32 weights (contiguous, unpadded)
__device__ __forceinline__ void load_w(float* dst, const float* __restrict__ src, int tid) {
    for (int i = tid * 4; i < 128 * 128; i += 1024)
        *reinterpret_cast<float4*>(dst + i) = *reinterpret_cast<const float4*>(src + i);
}

// ---------------- kernel 1: node embedding + norm ----------------------------
// h0 = norm(V @ Wv + b), one block (128 thr) per node row
__global__ void embed_node_kernel(const float* __restrict__ V,
                                  const float* __restrict__ W,
                                  const float* __restrict__ b,
                                  const float* __restrict__ g,
                                  const float* __restrict__ b2) {
    int row = blockIdx.x;
    int j = threadIdx.x;
    const float* v = V + row * 64;
    float acc = b[j];
#pragma unroll
    for (int k = 0; k < 64; ++k) acc = fmaf(__ldg(v + k), __ldg(W + k * HH + j), acc);

    __shared__ float red[8];
    float s = acc;
#pragma unroll
    for (int o = 16; o; o >>= 1) s += __shfl_xor_sync(0xffffffffu, s, o);
    int w = j >> 5, l = j & 31;
    if (l == 0) red[w] = s;
    __syncthreads();
    float mu = (red[0] + red[1] + red[2] + red[3]) * (1.f / 128.f);
    float d = acc - mu;
    float ss = d * d;
#pragma unroll
    for (int o = 16; o; o >>= 1) ss += __shfl_xor_sync(0xffffffffu, ss, o);
    if (l == 0) red[4 + w] = ss;
    __syncthreads();
    float var = (red[4] + red[5] + red[6] + red[7]) * (1.f / 127.f);
    float sigma = sqrtf(var);
    g_h[row * HH + j] = g[j] * d / (sigma + 1e-6f) + b2[j];
}

// ---------------- kernel 2: edge embedding + norm ----------------------------
// he = norm(E @ We + b), one block (128 thr) per edge row
__global__ void embed_edge_kernel(const float* __restrict__ E,
                                  const float* __restrict__ W,
                                  const float* __restrict__ b,
                                  const float* __restrict__ g,
                                  const float* __restrict__ b2) {
    int row = blockIdx.x;
    int j = threadIdx.x;
    const float* e = E + row * 48;
    float acc = b[j];
#pragma unroll
    for (int k = 0; k < 48; ++k) acc = fmaf(__ldg(e + k), __ldg(W + k * HH + j), acc);

    __shared__ float red[8];
    float s = acc;
#pragma unroll
    for (int o = 16; o; o >>= 1) s += __shfl_xor_sync(0xffffffffu, s, o);
    int w = j >> 5, l = j & 31;
    if (l == 0) red[w] = s;
    __syncthreads();
    float mu = (red[0] + red[1] + red[2] + red[3]) * (1.f / 128.f);
    float d = acc - mu;
    float ss = d * d;
#pragma unroll
    for (int o = 16; o; o >>= 1) ss += __shfl_xor_sync(0xffffffffu, ss, o);
    if (l == 0) red[4 + w] = ss;
    __syncthreads();
    float var = (red[4] + red[5] + red[6] + red[7]) * (1.f / 127.f);
    float sigma = sqrtf(var);
    g_he[row * HH + j] = g[j] * d / (sigma + 1e-6f) + b2[j];
}

// ---------------- kernel 3: per-layer node projections -----------------------
// y==0: P1  = h @ W1 + b1
// y==1: P23 = h @ W2 + hS @ W3
__global__ void __launch_bounds__(256, 1)
node_proj_kernel(const float* __restrict__ hS,
                 const float* __restrict__ Lw1,
                 const float* __restrict__ Lb1,
                 int layer) {
    extern __shared__ float sm[];
    float* sW = sm;
    float* sA = sm + 128 * 128;

    int tid = threadIdx.x;
    int base = blockIdx.x * 128;            // row base (node index)
    int which = blockIdx.y;
    const float* Wbase = Lw1 + (size_t)layer * 512 * 128;

    load_tile_pad(sA, g_h + (size_t)base * 128, tid);
    load_w(sW, Wbase + (which == 0 ? 0 : 128 * 128), tid);
    __syncthreads();

    int j0 = (tid & 15) * 8;
    int r0 = (tid >> 4) * 8;
    unsigned long long acc[8][4];
    zero_acc(acc);
    gemm_tile(sA, sW, r0, j0, acc);

    if (which == 1) {
        __syncthreads();
        load_tile_pad(sA, hS + (size_t)base * 128, tid);
        load_w(sW, Wbase + 256 * 128, tid);
        __syncthreads();
        gemm_tile(sA, sW, r0, j0, acc);     // accumulate
    }

    float bias[8];
    if (which == 0) {
        const float* b1 = Lb1 + layer * 128;
#pragma unroll
        for (int c = 0; c < 8; ++c) bias[c] = b1[j0 + c];
    } else {
#pragma unroll
        for (int c = 0; c < 8; ++c) bias[c] = 0.f;
    }
    float* out = (which == 0) ? g_P1 : g_P23;
#pragma unroll
    for (int i = 0; i < 8; ++i) {
        float2 a0 = u2f(acc[i][0]), a1 = u2f(acc[i][1]);
        float2 a2 = u2f(acc[i][2]), a3 = u2f(acc[i][3]);
        float4 o0 = make_float4(a0.x + bias[0], a0.y + bias[1], a1.x + bias[2], a1.y + bias[3]);
        float4 o1 = make_float4(a2.x + bias[4], a2.y + bias[5], a3.x + bias[6], a3.y + bias[7]);
        float* dst = out + (size_t)(base + r0 + i) * 128 + j0;
        *reinterpret_cast<float4*>(dst) = o0;
        *reinterpret_cast<float4*>(dst + 4) = o1;
    }
}

// ---------------- kernel 4: fused edge MLP + aggregate + residual norm -------
// One block = 4 nodes = 128 edge rows. Three chained 128x128x128 GEMMs in smem.
__global__ void __launch_bounds__(256, 1)
edge_layer_kernel(const int* __restrict__ Eidx,
                  const float* __restrict__ mask,
                  const float* __restrict__ Lw1,
                  const float* __restrict__ Lw2,
                  const float* __restrict__ Lw3,
                  const float* __restrict__ Lb2,
                  const float* __restrict__ Lb3,
                  const float* __restrict__ Lng,
                  const float* __restrict__ Lnb,
                  int layer,
                  float* h_out_opt) {
    extern __shared__ float sm[];
    float* sW    = sm;                     // 16384
    float* sA    = sW + 16384;             // 128*PAD = 16640
    float* sP1   = sA + 128 * PAD;         // 512
    float* sHold = sP1 + 512;              // 512
    float* sDh   = sHold + 512;            // 512
    float* sB2   = sDh + 512;              // 128
    float* sB3   = sB2 + 128;              // 128
    float* sVm   = sB3 + 128;              // 128
    int*   sGidx = reinterpret_cast<int*>(sVm + 128); // 128

    int tid = threadIdx.x;
    int base = blockIdx.x * 4;             // node base

    // ---- prologue
    if (tid < 128) {
        int r = tid;
        int nd = base + (r >> 5);
        int b = nd >> 11;
        int idx = Eidx[nd * 32 + (r & 31)];
        int gi = (b << 11) + idx;
        sGidx[r] = gi;
        sVm[r] = mask[gi];
        sB2[r] = Lb2[layer * 128 + r];
        sB3[r] = Lb3[layer * 128 + r];
    }
    for (int i = tid; i < 512; i += 256) {
        sP1[i]   = g_P1[(size_t)base * 128 + i];
        sHold[i] = g_h [(size_t)base * 128 + i];
    }
    load_tile_pad(sA, g_he + (size_t)base * 32 * 128, tid);      // he tile (128 rows)
    load_w(sW, Lw1 + (size_t)layer * 512 * 128 + 384 * 128, tid); // W4
    __syncthreads();

    int j0 = (tid & 15) * 8;
    int r0 = (tid >> 4) * 8;
    unsigned long long acc[8][4];

    // ---- GEMM1: pre = he@W4 (+ P1[node] + P23[gather] + relu in epilogue)
    zero_acc(acc);
    gemm_tile(sA, sW, r0, j0, acc);
    __syncthreads();
#pragma unroll
    for (int i = 0; i < 8; ++i) {
        int r = r0 + i;
        const float* p23 = g_P23 + (size_t)sGidx[r] * 128 + j0;
        float4 q0 = *reinterpret_cast<const float4*>(p23);
        float4 q1 = *reinterpret_cast<const float4*>(p23 + 4);
        const float* p1 = sP1 + ((r >> 5) << 7) + j0;
        float2 a0 = u2f(acc[i][0]), a1 = u2f(acc[i][1]);
        float2 a2 = u2f(acc[i][2]), a3 = u2f(acc[i][3]);
        float2 o0 = make_float2(fmaxf(a0.x + q0.x + p1[0], 0.f), fmaxf(a0.y + q0.y + p1[1], 0.f));
        float2 o1 = make_float2(fmaxf(a1.x + q0.z + p1[2], 0.f), fmaxf(a1.y + q0.w + p1[3], 0.f));
        float2 o2 = make_float2(fmaxf(a2.x + q1.x + p1[4], 0.f), fmaxf(a2.y + q1.y + p1[5], 0.f));
        float2 o3 = make_float2(fmaxf(a3.x + q1.z + p1[6], 0.f), fmaxf(a3.y + q1.w + p1[7], 0.f));
        float* dst = sA + r * PAD + j0;
        *reinterpret_cast<float2*>(dst)     = o0;
        *reinterpret_cast<float2*>(dst + 2) = o1;
        *reinterpret_cast<float2*>(dst + 4) = o2;
        *reinterpret_cast<float2*>(dst + 6) = o3;
    }
    load_w(sW, Lw2 + (size_t)layer * 128 * 128, tid);
    __syncthreads();

    // ---- GEMM2: m2 = relu(m1@Lw2 + b2)
    zero_acc(acc);
    gemm_tile(sA, sW, r0, j0, acc);
    __syncthreads();
#pragma unroll
    for (int i = 0; i < 8; ++i) {
        int r = r0 + i;
        float2 a0 = u2f(acc[i][0]), a1 = u2f(acc[i][1]);
        float2 a2 = u2f(acc[i][2]), a3 = u2f(acc[i][3]);
        const float* b2p = sB2 + j0;
        float2 o0 = make_float2(fmaxf(a0.x + b2p[0], 0.f), fmaxf(a0.y + b2p[1], 0.f));
        float2 o1 = make_float2(fmaxf(a1.x + b2p[2], 0.f), fmaxf(a1.y + b2p[3], 0.f));
        float2 o2 = make_float2(fmaxf(a2.x + b2p[4], 0.f), fmaxf(a2.y + b2p[5], 0.f));
        float2 o3 = make_float2(fmaxf(a3.x + b2p[6], 0.f), fmaxf(a3.y + b2p[7], 0.f));
        float* dst = sA + r * PAD + j0;
        *reinterpret_cast<float2*>(dst)     = o0;
        *reinterpret_cast<float2*>(dst + 2) = o1;
        *reinterpret_cast<float2*>(dst + 4) = o2;
        *reinterpret_cast<float2*>(dst + 6) = o3;
    }
    load_w(sW, Lw3 + (size_t)layer * 128 * 128, tid);
    __syncthreads();

    // ---- GEMM3: m3 = (m2@Lw3 + b3) * vmask
    zero_acc(acc);
    gemm_tile(sA, sW, r0, j0, acc);
    __syncthreads();
#pragma unroll
    for (int i = 0; i < 8; ++i) {
        int r = r0 + i;
        float vm = sVm[r];
        float2 a0 = u2f(acc[i][0]), a1 = u2f(acc[i][1]);
        float2 a2 = u2f(acc[i][2]), a3 = u2f(acc[i][3]);
        const float* b3p = sB3 + j0;
        float2 o0 = make_float2((a0.x + b3p[0]) * vm, (a0.y + b3p[1]) * vm);
        float2 o1 = make_float2((a1.x + b3p[2]) * vm, (a1.y + b3p[3]) * vm);
        float2 o2 = make_float2((a2.x + b3p[4]) * vm, (a2.y + b3p[5]) * vm);
        float2 o3 = make_float2((a3.x + b3p[6]) * vm, (a3.y + b3p[7]) * vm);
        float* dst = sA + r * PAD + j0;
        *reinterpret_cast<float2*>(dst)     = o0;
        *reinterpret_cast<float2*>(dst + 2) = o1;
        *reinterpret_cast<float2*>(dst + 4) = o2;
        *reinterpret_cast<float2*>(dst + 6) = o3;
    }
    __syncthreads();

    // ---- segment sum over K=32 edges per node -> dh
    for (int p = tid; p < 512; p += 256) {
        int g = p >> 7, j = p & 127;
        const float* col = sA + (g * 32) * PAD + j;
        float s = 0.f;
#pragma unroll
        for (int r = 0; r < 32; ++r) s += col[r * PAD];
        sDh[p] = s * (1.f / 30.f);
    }
    __syncthreads();

    // ---- residual + layernorm (ddof=1) + mask; warp per node
    float* hout = h_out_opt ? h_out_opt : g_h;
    int w = tid >> 5, l = tid & 31;
    if (w < 4) {
        int nd = base + w;
        float x[4], sum = 0.f;
#pragma unroll
        for (int c = 0; c < 4; ++c) {
            int j = l + 32 * c;
            x[c] = sHold[w * 128 + j] + sDh[w * 128 + j];
            sum += x[c];
        }
#pragma unroll
        for (int o = 16; o; o >>= 1) sum += __shfl_xor_sync(0xffffffffu, sum, o);
        float mu = sum * (1.f / 128.f);
        float ss = 0.f;
#pragma unroll
        for (int c = 0; c < 4; ++c) {
            float d = x[c] - mu;
            ss += d * d;
        }
#pragma unroll
        for (int o = 16; o; o >>= 1) ss += __shfl_xor_sync(0xffffffffu, ss, o);
        float sigma = sqrtf(ss * (1.f / 127.f));
        float inv = 1.f / (sigma + 1e-6f);
        float mk = mask[nd];
#pragma unroll
        for (int c = 0; c < 4; ++c) {
            int j = l + 32 * c;
            float v = (Lng[layer * 128 + j] * (x[c] - mu) * inv + Lnb[layer * 128 + j]) * mk;
            hout[(size_t)nd * 128 + j] = v;
        }
    }
}

// ---------------- launch ------------------------------------------------------
extern "C" void kernel_launch(void* const* d_in, const int* in_sizes, int n_in,
                              void* d_out, int out_size) {
    const float* V     = (const float*)d_in[0];
    const float* E     = (const float*)d_in[1];
    const float* hS    = (const float*)d_in[2];
    const int*   E_idx = (const int*)  d_in[3];
    const float* mask  = (const float*)d_in[4];
    const float* Wv_w  = (const float*)d_in[5];
    const float* Wv_b  = (const float*)d_in[6];
    const float* Wv_g  = (const float*)d_in[7];
    const float* Wv_b2 = (const float*)d_in[8];
    const float* We_w  = (const float*)d_in[9];
    const float* We_b  = (const float*)d_in[10];
    const float* We_g  = (const float*)d_in[11];
    const float* We_b2 = (const float*)d_in[12];
    const float* Lw1   = (const float*)d_in[13];
    const float* Lb1   = (const float*)d_in[14];
    const float* Lw2   = (const float*)d_in[15];
    const float* Lb2   = (const float*)d_in[16];
    const float* Lw3   = (const float*)d_in[17];
    const float* Lb3   = (const float*)d_in[18];
    const float* Ln_g  = (const float*)d_in[19];
    const float* Ln_b  = (const float*)d_in[20];
    float* out = (float*)d_out;

    const int PROJ_SMEM = (128 * 128 + 128 * PAD) * 4;                       // 132096
    const int EDGE_SMEM = (128 * 128 + 128 * PAD + 512 * 3 + 128 * 3 + 128) * 4; // 140288
    cudaFuncSetAttribute(node_proj_kernel,  cudaFuncAttributeMaxDynamicSharedMemorySize, PROJ_SMEM);
    cudaFuncSetAttribute(edge_layer_kernel, cudaFuncAttributeMaxDynamicSharedMemorySize, EDGE_SMEM);

    embed_node_kernel<<<NODES, 128>>>(V, Wv_w, Wv_b, Wv_g, Wv_b2);
    embed_edge_kernel<<<EDGES, 128>>>(E, We_w, We_b, We_g, We_b2);

    for (int layer = 0; layer < 3; ++layer) {
        node_proj_kernel<<<dim3(NODES / 128, 2), 256, PROJ_SMEM>>>(hS, Lw1, Lb1, layer);
        float* hdst = (layer == 2) ? out : nullptr;   // nullptr -> write g_h in-place
        edge_layer_kernel<<<NODES / 4, 256, EDGE_SMEM>>>(
            E_idx, mask, Lw1, Lw2, Lw3, Lb2, Lb3, Ln_g, Ln_b, layer, hdst);
    }
}